// round 14
// baseline (speedup 1.0000x reference)
#include <cuda_runtime.h>

// TAHE: masked cosine-similarity weighted pooling.
// out[b,d] = sum_l [ts[b,l]>0] * (dot(cur_n[b], rec_n[b,l]) + 1)/2 * emb[b,l,d]
//
// R14: R13 (1 row / 128-thread CTA, grid=4096, 1.73 waves) plus CTA-wide
//   compaction with warp-STRIDED assignment: one combined active list per
//   row; warp w processes positions {w, w+4, ...} -> each warp gets
//   total/4 +-1 items (removes the Binomial max-of-4 intra-CTA imbalance
//   that left the CTA waiting on its slowest warp). Phases stay decoupled:
//   each warp writes and reads only its own strided weight entries.

#define TAHE_B 4096
#define TAHE_L 200
#define TAHE_D 128
#define WARPS_PER_CTA 4
#define L_QTR 50               // compaction range per warp

__global__ __launch_bounds__(WARPS_PER_CTA * 32, 16)
void tahe_kernel(const float* __restrict__ rec,
                 const float* __restrict__ cur,
                 const int*   __restrict__ ts,
                 const float* __restrict__ emb,
                 float*       __restrict__ out) {
    __shared__ short s_q   [WARPS_PER_CTA][L_QTR + 2];  // per-warp staging
    __shared__ int   s_cnt [WARPS_PER_CTA];
    __shared__ short s_list[TAHE_L + 8];                // combined active list
    __shared__ float s_w   [TAHE_L + 8];                // weights (strided owner)
    __shared__ float s_part[WARPS_PER_CTA][TAHE_D];

    const int warp = threadIdx.x >> 5;
    const int lane = threadIdx.x & 31;
    const int b    = blockIdx.x;

    const unsigned lanemask_lt = (1u << lane) - 1u;

    // ---- normalize current representation (lane owns 4 contiguous floats) ----
    float4 c = reinterpret_cast<const float4*>(cur + (size_t)b * TAHE_D)[lane];
    float csq = c.x * c.x + c.y * c.y + c.z * c.z + c.w * c.w;
    #pragma unroll
    for (int o = 16; o > 0; o >>= 1)
        csq += __shfl_xor_sync(0xFFFFFFFFu, csq, o);
    const float cinv = rsqrtf(fmaxf(csq, 1e-12f));
    c.x *= cinv; c.y *= cinv; c.z *= cinv; c.w *= cinv;

    // ---- per-warp compaction of its L-quarter into staging ----
    const int* tsb = ts + (size_t)b * TAHE_L + warp * L_QTR;
    int qcnt = 0;
    #pragma unroll
    for (int chunk = 0; chunk < 2; chunk++) {           // 2*32 = 64 >= 50
        const int li = chunk * 32 + lane;
        const int t  = (li < L_QTR) ? tsb[li] : 0;
        const unsigned ballot = __ballot_sync(0xFFFFFFFFu, t > 0);
        if (t > 0)
            s_q[warp][qcnt + __popc(ballot & lanemask_lt)] =
                (short)(warp * L_QTR + li);
        qcnt += __popc(ballot);
    }
    if (lane == 0) s_cnt[warp] = qcnt;
    __syncthreads();

    // ---- merge into one combined list; compute warp's strided share ----
    int base = 0;
    #pragma unroll
    for (int k = 0; k < WARPS_PER_CTA; k++) base += (k < warp) ? s_cnt[k] : 0;
    const int total = s_cnt[0] + s_cnt[1] + s_cnt[2] + s_cnt[3];
    for (int i = lane; i < qcnt; i += 32) s_list[base + i] = s_q[warp][i];
    __syncthreads();

    // warp w owns combined-list positions w, w+4, w+8, ... (total/4 +- 1 each)
    const int mycnt = (total > warp) ? ((total - warp + 3) >> 2) : 0;
    #define POS(j) (warp + 4 * (j))

    const float4* recb = reinterpret_cast<const float4*>(rec + (size_t)b * TAHE_L * TAHE_D);
    const float4* embb = reinterpret_cast<const float4*>(emb + (size_t)b * TAHE_L * TAHE_D);

    // ================= Phase 1: weights (rec only, pipelined) =================
    {
        int j = 0;
        if (mycnt >= 2) {
            float4 ra = __ldcs(&recb[(size_t)s_list[POS(0)] * 32 + lane]);
            float4 rb = __ldcs(&recb[(size_t)s_list[POS(1)] * 32 + lane]);

            for (;;) {
                float d0 = ra.x*c.x + ra.y*c.y + ra.z*c.z + ra.w*c.w;
                float s0 = ra.x*ra.x + ra.y*ra.y + ra.z*ra.z + ra.w*ra.w;
                float d1 = rb.x*c.x + rb.y*c.y + rb.z*c.z + rb.w*c.w;
                float s1 = rb.x*rb.x + rb.y*rb.y + rb.z*rb.z + rb.w*rb.w;

                // prefetch next pair while the shuffle chain runs
                const int jj = j + 2;
                const bool more = (jj + 2 <= mycnt);
                const int n0 = more ? (int)s_list[POS(jj)]     : 0;
                const int n1 = more ? (int)s_list[POS(jj + 1)] : 0;
                ra = __ldcs(&recb[(size_t)n0 * 32 + lane]);
                rb = __ldcs(&recb[(size_t)n1 * 32 + lane]);

                #pragma unroll
                for (int o = 16; o > 0; o >>= 1) {
                    d0 += __shfl_xor_sync(0xFFFFFFFFu, d0, o);
                    s0 += __shfl_xor_sync(0xFFFFFFFFu, s0, o);
                    d1 += __shfl_xor_sync(0xFFFFFFFFu, d1, o);
                    s1 += __shfl_xor_sync(0xFFFFFFFFu, s1, o);
                }

                if (lane == 0) {
                    s_w[POS(j)]     = (d0 * rsqrtf(fmaxf(s0, 1e-12f)) + 1.0f) * 0.5f;
                    s_w[POS(j + 1)] = (d1 * rsqrtf(fmaxf(s1, 1e-12f)) + 1.0f) * 0.5f;
                }

                j = jj;
                if (!more) break;
            }
        }
        if (mycnt & 1) {
            const int p = POS(mycnt - 1);
            const float4 r0 = __ldcs(&recb[(size_t)s_list[p] * 32 + lane]);
            float d0 = r0.x*c.x + r0.y*c.y + r0.z*c.z + r0.w*c.w;
            float s0 = r0.x*r0.x + r0.y*r0.y + r0.z*r0.z + r0.w*r0.w;
            #pragma unroll
            for (int o = 16; o > 0; o >>= 1) {
                d0 += __shfl_xor_sync(0xFFFFFFFFu, d0, o);
                s0 += __shfl_xor_sync(0xFFFFFFFFu, s0, o);
            }
            if (lane == 0)
                s_w[p] = (d0 * rsqrtf(fmaxf(s0, 1e-12f)) + 1.0f) * 0.5f;
        }
    }
    __syncwarp();

    // ================= Phase 2: pooling (emb only, pure stream) ===============
    float4 accA = make_float4(0.f, 0.f, 0.f, 0.f);
    float4 accB = make_float4(0.f, 0.f, 0.f, 0.f);

    int j = 0;
    for (; j + 4 <= mycnt; j += 4) {
        const int p0 = POS(j), p1 = POS(j + 1), p2 = POS(j + 2), p3 = POS(j + 3);
        const int l0 = s_list[p0];
        const int l1 = s_list[p1];
        const int l2 = s_list[p2];
        const int l3 = s_list[p3];
        const float w0 = s_w[p0];
        const float w1 = s_w[p1];
        const float w2 = s_w[p2];
        const float w3 = s_w[p3];

        const float4 e0 = __ldcs(&embb[(size_t)l0 * 32 + lane]);
        const float4 e1 = __ldcs(&embb[(size_t)l1 * 32 + lane]);
        const float4 e2 = __ldcs(&embb[(size_t)l2 * 32 + lane]);
        const float4 e3 = __ldcs(&embb[(size_t)l3 * 32 + lane]);

        accA.x = fmaf(w0, e0.x, fmaf(w1, e1.x, accA.x));
        accA.y = fmaf(w0, e0.y, fmaf(w1, e1.y, accA.y));
        accA.z = fmaf(w0, e0.z, fmaf(w1, e1.z, accA.z));
        accA.w = fmaf(w0, e0.w, fmaf(w1, e1.w, accA.w));
        accB.x = fmaf(w2, e2.x, fmaf(w3, e3.x, accB.x));
        accB.y = fmaf(w2, e2.y, fmaf(w3, e3.y, accB.y));
        accB.z = fmaf(w2, e2.z, fmaf(w3, e3.z, accB.z));
        accB.w = fmaf(w2, e2.w, fmaf(w3, e3.w, accB.w));
    }
    for (; j < mycnt; j++) {
        const int p0 = POS(j);
        const int l0 = s_list[p0];
        const float w0 = s_w[p0];
        const float4 e0 = __ldcs(&embb[(size_t)l0 * 32 + lane]);
        accA.x = fmaf(w0, e0.x, accA.x);
        accA.y = fmaf(w0, e0.y, accA.y);
        accA.z = fmaf(w0, e0.z, accA.z);
        accA.w = fmaf(w0, e0.w, accA.w);
    }
    const float4 acc = make_float4(accA.x + accB.x, accA.y + accB.y,
                                   accA.z + accB.z, accA.w + accB.w);

    // ---- combine the four warps (fixed order -> deterministic) ----
    reinterpret_cast<float4*>(s_part[warp])[lane] = acc;
    __syncthreads();

    const int t = threadIdx.x;           // 0..127 -> one output element each
    const float v = s_part[0][t] + s_part[1][t] + s_part[2][t] + s_part[3][t];
    out[(size_t)b * TAHE_D + t] = v;
}

extern "C" void kernel_launch(void* const* d_in, const int* in_sizes, int n_in,
                              void* d_out, int out_size) {
    const float* rec = (const float*)d_in[0];
    const float* cur = (const float*)d_in[1];
    const int*   ts  = (const int*)  d_in[2];
    const float* emb = (const float*)d_in[3];
    float*       out = (float*)d_out;

    tahe_kernel<<<TAHE_B, WARPS_PER_CTA * 32>>>(rec, cur, ts, emb, out);
}